// round 8
// baseline (speedup 1.0000x reference)
#include <cuda_runtime.h>
#include <math.h>

#define B 8
#define D 4096
#define H 32
#define KVH 8
#define HD 128
#define M 4096
#define NREP 4
#define NCOLS (H*HD + 2*KVH*HD)   /* 6144 */
#define NSPLIT1 64
#define ICH1 (D/NSPLIT1)          /* 64 */
#define NSPLIT2 64
#define ICH2 (D/NSPLIT2)          /* 64 */
#define MSPLIT 32
#define MC (M/MSPLIT)             /* 128 */
#define TILE 32
#define NT (MC/TILE)              /* 4 */
#define NU (2*NT)                 /* 8 unified tiles: 4 K then 4 V */
#define SCALE 0.08838834764831845f
#define FULLMASK 0xffffffffu

// attn smem (floats): THREE tile buffers (32 rows x 33 float4), Q, scores
#define TB_F (32*33*4)            /* 4224 floats per tile buffer */
#define SM_Q  (3*TB_F)            /* 12672 */
#define SM_SC (SM_Q+512)          /* 13184: sc[128][4] */
#define SM_FLOATS (SM_SC+512)     /* 13696 -> 54784 B */
#define SMEM_BYTES (SM_FLOATS*4)

// ---------------- static device scratch ----------------
__device__ __align__(16) float g_qkv_part[NSPLIT1][B][NCOLS];
__device__ __align__(16) float g_q[B][H*HD];
__device__ __align__(16) float g_knew[B][KVH][HD];
__device__ __align__(16) float g_vnew[B][KVH][HD];
__device__ __align__(16) float g_part_o[B][KVH][MSPLIT][NREP][HD];
__device__ float g_part_m[B][KVH][MSPLIT][NREP];
__device__ float g_part_l[B][KVH][MSPLIT][NREP];
__device__ __align__(16) float g_out_part[NSPLIT2][B][D];

__device__ __forceinline__ void cp16(void* dst, const void* src) {
    unsigned u = (unsigned)__cvta_generic_to_shared(dst);
    asm volatile("cp.async.cg.shared.global [%0], [%1], 16;" :: "r"(u), "l"(src));
}
#define CP_COMMIT() asm volatile("cp.async.commit_group;")
#define CP_WAIT1()  asm volatile("cp.async.wait_group 1;" ::: "memory")

// ---------------- kernel 1: QKV projection (split-K GEMV, float4 cols, 128 thr) ----------------
__global__ __launch_bounds__(128) void proj_qkv(const float* __restrict__ x,
                         const float* __restrict__ wq,
                         const float* __restrict__ wk, const float* __restrict__ wv) {
    __shared__ float xs[B][ICH1];
    const int tid = threadIdx.x;
    const int j4 = blockIdx.x * 128 + tid;       // float4 column index (0..1535)
    const int j = 4 * j4;
    const int i0 = blockIdx.y * ICH1;

    for (int idx = tid; idx < B * ICH1; idx += 128) {
        int b = idx / ICH1, ii = idx % ICH1;
        xs[b][ii] = x[b * D + i0 + ii];
    }
    __syncthreads();

    const float* w; int stride, jl;
    if (j < H*HD)                 { w = wq; stride = H*HD;  jl = j; }
    else if (j < H*HD + KVH*HD)   { w = wk; stride = KVH*HD; jl = j - H*HD; }
    else                          { w = wv; stride = KVH*HD; jl = j - H*HD - KVH*HD; }
    const float* wp = w + (size_t)i0 * stride + jl;

    float4 acc[B];
    #pragma unroll
    for (int b = 0; b < B; b++) acc[b] = make_float4(0.f,0.f,0.f,0.f);

    #pragma unroll 4
    for (int ii = 0; ii < ICH1; ii++) {
        float4 w4 = *(const float4*)(wp + (size_t)ii * stride);
        #pragma unroll
        for (int b = 0; b < B; b++) {
            float xv = xs[b][ii];
            acc[b].x = fmaf(xv, w4.x, acc[b].x);
            acc[b].y = fmaf(xv, w4.y, acc[b].y);
            acc[b].z = fmaf(xv, w4.z, acc[b].z);
            acc[b].w = fmaf(xv, w4.w, acc[b].w);
        }
    }
    #pragma unroll
    for (int b = 0; b < B; b++)
        *(float4*)&g_qkv_part[blockIdx.y][b][j] = acc[b];
}

// ---------------- kernel 2: reduce partials + RoPE + scatter (float4 per thread) ----------------
__global__ __launch_bounds__(256) void rope_scatter(const float* __restrict__ fcos,
                                                    const float* __restrict__ fsin) {
    const int t = blockIdx.x * 256 + threadIdx.x;   // float4 id over B*NCOLS/4
    const int b  = t / (NCOLS / 4);
    const int q4 = t % (NCOLS / 4);
    const int j0 = 4 * q4;

    float4 v = make_float4(0.f, 0.f, 0.f, 0.f);
    #pragma unroll
    for (int s = 0; s < NSPLIT1; s++) {
        float4 p = *(const float4*)&g_qkv_part[s][b][j0];
        v.x += p.x; v.y += p.y; v.z += p.z; v.w += p.w;
    }

    if (j0 < H*HD) {                                      // q + RoPE, pre-scaled
        int p = (j0 & (HD-1)) >> 1;
        float c0 = fcos[p] * SCALE,   s0 = fsin[p] * SCALE;
        float c1 = fcos[p+1] * SCALE, s1 = fsin[p+1] * SCALE;
        float4 o;
        o.x = v.x * c0 - v.y * s0;
        o.y = v.x * s0 + v.y * c0;
        o.z = v.z * c1 - v.w * s1;
        o.w = v.z * s1 + v.w * c1;
        *(float4*)&g_q[b][j0] = o;
    } else if (j0 < H*HD + KVH*HD) {                      // k + RoPE
        int l = j0 - H*HD; int kvh = l >> 7; int d = l & (HD-1); int p = d >> 1;
        float c0 = fcos[p],   s0 = fsin[p];
        float c1 = fcos[p+1], s1 = fsin[p+1];
        float4 o;
        o.x = v.x * c0 - v.y * s0;
        o.y = v.x * s0 + v.y * c0;
        o.z = v.z * c1 - v.w * s1;
        o.w = v.z * s1 + v.w * c1;
        *(float4*)&g_knew[b][kvh][d] = o;
    } else {                                              // v
        int l = j0 - H*HD - KVH*HD; int kvh = l >> 7; int d = l & (HD-1);
        *(float4*)&g_vnew[b][kvh][d] = v;
    }
}

// ---------------- kernel 3: 3-stage-pipelined flash-decode attention + cache emit ----------------
__device__ __forceinline__ void issue_tile(float* sm, int u, int tid, int m_start,
                                           const float4* Kg, const float4* Vg) {
    const float4* src = (u < NT) ? Kg : Vg;
    const int mt = (u < NT) ? u : u - NT;
    const int fb = (m_start + mt * TILE) * 32;
    float4* Nb = (float4*)sm + (u % 3) * (TB_F/4);
    #pragma unroll
    for (int i = 0; i < 4; i++) {
        int ff = tid + i * 256, row = ff >> 5, c4 = ff & 31;
        cp16(&Nb[row*33 + c4], &src[fb + ff]);
    }
}

__global__ __launch_bounds__(256, 4) void attn_pass1(
        const float* __restrict__ cache_k, const float* __restrict__ cache_v,
        const float* __restrict__ mask, const int* __restrict__ pos_p,
        float* __restrict__ out_k, float* __restrict__ out_v) {
    extern __shared__ float sm[];
    float* Qs = sm + SM_Q;
    float* sc = sm + SM_SC;

    const int bx = blockIdx.x;
    const int split = bx % MSPLIT;
    const int kvh = (bx / MSPLIT) % KVH;
    const int b = bx / (MSPLIT * KVH);
    const int tid = threadIdx.x;
    const int pos = pos_p[0];

    const size_t base = (size_t)(b * KVH + kvh) * M * HD;
    const float4* Kg = (const float4*)(cache_k + base);
    const float4* Vg = (const float4*)(cache_v + base);
    float4* Kog = (float4*)(out_k + base);
    float4* Vog = (float4*)(out_v + base);
    const float4* knew4 = (const float4*)&g_knew[b][kvh][0];
    const float4* vnew4 = (const float4*)&g_vnew[b][kvh][0];

    const int m_start = split * MC;

    issue_tile(sm, 0, tid, m_start, Kg, Vg); CP_COMMIT();
    issue_tile(sm, 1, tid, m_start, Kg, Vg); CP_COMMIT();

    #pragma unroll
    for (int i = 0; i < 2; i++)
        Qs[tid + i * 256] = g_q[b][kvh * NREP * HD + tid + i * 256];

    const int r = tid >> 2;
    const int h = tid & 3;
    const int d = tid & 127;
    const int h0 = (tid >> 7) * 2, h1 = h0 + 1;
    const float* maskp = mask + ((size_t)(b * H) + kvh * NREP + h) * M;

    float o0 = 0.f, o1 = 0.f;

    for (int u = 0; u < NU; u++) {
        float4* Sb = (float4*)sm + (u % 3) * (TB_F/4);
        const bool isK = (u < NT);
        const int mt = isK ? u : u - NT;
        const int m0 = m_start + mt * TILE;

        CP_WAIT1();
        __syncthreads();

        if (u == NT) {
            if (tid < 128) {
                const int w = tid >> 5, ln = tid & 31;
                float s0 = sc[(ln      ) * 4 + w];
                float s1 = sc[(ln + 32 ) * 4 + w];
                float s2 = sc[(ln + 64 ) * 4 + w];
                float s3 = sc[(ln + 96 ) * 4 + w];
                float v = fmaxf(fmaxf(s0, s1), fmaxf(s2, s3));
                #pragma unroll
                for (int off = 16; off; off >>= 1)
                    v = fmaxf(v, __shfl_xor_sync(FULLMASK, v, off));
                float e0 = __expf(s0 - v), e1 = __expf(s1 - v);
                float e2 = __expf(s2 - v), e3 = __expf(s3 - v);
                sc[(ln      ) * 4 + w] = e0;
                sc[(ln + 32 ) * 4 + w] = e1;
                sc[(ln + 64 ) * 4 + w] = e2;
                sc[(ln + 96 ) * 4 + w] = e3;
                float l = e0 + e1 + e2 + e3;
                #pragma unroll
                for (int off = 16; off; off >>= 1)
                    l += __shfl_xor_sync(FULLMASK, l, off);
                if (ln == 0) {
                    g_part_m[b][kvh][split][w] = v;
                    g_part_l[b][kvh][split][w] = l;
                }
            }
            __syncthreads();
        }

        if (u + 2 < NU) issue_tile(sm, u + 2, tid, m_start, Kg, Vg);
        CP_COMMIT();

        if (pos >= m0 && pos < m0 + TILE) {
            const float4* nsrc = isK ? knew4 : vnew4;
            if (tid < 32) Sb[(pos - m0)*33 + tid] = nsrc[tid];
            __syncthreads();
        }

        if (isK) {
            if (tid < 128) {
                const float4* krow = Sb + r * 33;
                const float4* qrow = (const float4*)Qs + h * 32;
                float acc = 0.f;
                #pragma unroll
                for (int i = 0; i < 32; i++) {
                    float4 k = krow[i], q = qrow[i];
                    acc = fmaf(k.x, q.x, acc);
                    acc = fmaf(k.y, q.y, acc);
                    acc = fmaf(k.z, q.z, acc);
                    acc = fmaf(k.w, q.w, acc);
                }
                sc[(mt * TILE + r) * 4 + h] = acc + maskp[m0 + r];
            } else {
                const int et = tid - 128;
                const int fb = m0 * 32;
                #pragma unroll
                for (int i = 0; i < 8; i++) {
                    int ff = et + i * 128, row = ff >> 5, c4 = ff & 31;
                    Kog[fb + ff] = Sb[row*33 + c4];
                }
            }
        } else {
            const float* Vf = (const float*)Sb;
            #pragma unroll 4
            for (int m = 0; m < TILE; m++) {
                float vv = Vf[m * 132 + d];
                int gr = mt * TILE + m;
                o0 = fmaf(sc[gr * 4 + h0], vv, o0);
                o1 = fmaf(sc[gr * 4 + h1], vv, o1);
            }
            {
                const int fb = m0 * 32;
                #pragma unroll
                for (int i = 0; i < 4; i++) {
                    int ff = tid + i * 256, row = ff >> 5, c4 = ff & 31;
                    Vog[fb + ff] = Sb[row*33 + c4];
                }
            }
        }
    }

    g_part_o[b][kvh][split][h0][d] = o0;
    g_part_o[b][kvh][split][h1][d] = o1;
}

// ---------------- kernel 4: output projection (fused combine + split-K GEMV, 128 thr) ----------------
__global__ __launch_bounds__(128) void oproj(const float* __restrict__ wo) {
    __shared__ float xs[B][ICH2];
    const int tid = threadIdx.x;
    const int i0 = blockIdx.y * ICH2;

    // prologue: reconstruct attention output slice from split partials
    for (int e = tid; e < B * ICH2; e += 128) {
        int bb = e >> 6, ii = e & 63;
        int jc = i0 + ii;
        int kvh = jc >> 9, hh = (jc >> 7) & 3, dd = jc & 127;
        float Mx = -1e30f;
        #pragma unroll
        for (int s = 0; s < MSPLIT; s++) Mx = fmaxf(Mx, g_part_m[bb][kvh][s][hh]);
        float L = 0.f, O = 0.f;
        #pragma unroll
        for (int s = 0; s < MSPLIT; s++) {
            float ee = __expf(g_part_m[bb][kvh][s][hh] - Mx);
            L += g_part_l[bb][kvh][s][hh] * ee;
            O += g_part_o[bb][kvh][s][hh][dd] * ee;
        }
        xs[bb][ii] = O / L;
    }
    __syncthreads();

    const int j4 = blockIdx.x * 128 + tid;       // float4 column (0..1023)
    const int j = 4 * j4;
    const float* wp = wo + (size_t)i0 * D + j;

    float4 acc[B];
    #pragma unroll
    for (int b = 0; b < B; b++) acc[b] = make_float4(0.f, 0.f, 0.f, 0.f);

    #pragma unroll 4
    for (int ii = 0; ii < ICH2; ii++) {
        float4 w4 = *(const float4*)(wp + (size_t)ii * D);
        #pragma unroll
        for (int b = 0; b < B; b++) {
            float xv = xs[b][ii];
            acc[b].x = fmaf(xv, w4.x, acc[b].x);
            acc[b].y = fmaf(xv, w4.y, acc[b].y);
            acc[b].z = fmaf(xv, w4.z, acc[b].z);
            acc[b].w = fmaf(xv, w4.w, acc[b].w);
        }
    }
    #pragma unroll
    for (int b = 0; b < B; b++)
        *(float4*)&g_out_part[blockIdx.y][b][j] = acc[b];
}

// ---------------- kernel 5: final reduce -> d_out (float4) ----------------
__global__ __launch_bounds__(128) void oproj_reduce(float* __restrict__ out) {
    const int t = blockIdx.x * 128 + threadIdx.x;   // float4 id over B*D/4
    const int b = t / (D/4), j4 = t % (D/4);
    float4 a = make_float4(0.f, 0.f, 0.f, 0.f);
    #pragma unroll
    for (int s = 0; s < NSPLIT2; s++) {
        float4 p = *(const float4*)&g_out_part[s][b][4*j4];
        a.x += p.x; a.y += p.y; a.z += p.z; a.w += p.w;
    }
    *(float4*)&out[(size_t)b * D + 4*j4] = a;
}

// ---------------- launch ----------------
extern "C" void kernel_launch(void* const* d_in, const int* in_sizes, int n_in,
                              void* d_out, int out_size) {
    const float* x        = (const float*)d_in[0];
    const float* fcos     = (const float*)d_in[1];
    const float* fsin     = (const float*)d_in[2];
    const float* mask     = (const float*)d_in[3];
    const float* cache_k  = (const float*)d_in[4];
    const float* cache_v  = (const float*)d_in[5];
    const int*   in_idx   = (const int*)d_in[7];
    const float* wq       = (const float*)d_in[9];
    const float* wk       = (const float*)d_in[10];
    const float* wv       = (const float*)d_in[11];
    const float* wo       = (const float*)d_in[12];

    float* out   = (float*)d_out;
    float* out_k = out + (size_t)B * D;
    float* out_v = out_k + (size_t)B * KVH * M * HD;

    static int smem_set = 0;
    if (!smem_set) {
        cudaFuncSetAttribute(attn_pass1, cudaFuncAttributeMaxDynamicSharedMemorySize, SMEM_BYTES);
        smem_set = 1;
    }

    proj_qkv<<<dim3(NCOLS / 512, NSPLIT1), 128>>>(x, wq, wk, wv);
    rope_scatter<<<(B * NCOLS / 4) / 256, 256>>>(fcos, fsin);
    attn_pass1<<<B * KVH * MSPLIT, 256, SMEM_BYTES>>>(cache_k, cache_v, mask, in_idx, out_k, out_v);
    oproj<<<dim3(D / 512, NSPLIT2), 128>>>(wo);
    oproj_reduce<<<(B * D / 4) / 128, 128>>>(out);
}